// round 16
// baseline (speedup 1.0000x reference)
#include <cuda_runtime.h>
#include <cuda_fp16.h>
#include <cstdint>

#define H     512
#define NLAY  4
#define N2    32
#define BSZ   8
#define LSEQ  4096
#define MROWS (BSZ * LSEQ)      /* 32768 */
#define NC    32                /* chunks per sequence */
#define CL    (LSEQ / NC)       /* 128 */
#define NINST (BSZ * NC)        /* 256 instances per h */
#define LN_EPS 1e-5f

// ---- static scratch ----
__device__ __align__(256) __half g_x16A[(size_t)MROWS * H];   // residual fp16 ping
__device__ __align__(256) __half g_x16B[(size_t)MROWS * H];   // residual fp16 pong
__device__ __align__(256) __half g_Uhi [(size_t)MROWS * H];   // u (B,H,L)
__device__ __align__(256) __half g_Yt16[(size_t)MROWS * H];   // gelu(y) (B,H,L)
__device__ __align__(256) __half g_Whi[(size_t)NLAY * 2 * H * H];
__device__ __align__(256) float g_bint[NLAY * 2 * H];
__device__ __align__(256) __half g_Zh[(size_t)MROWS * H];     // GLU out (B,L,H)
// Toeplitz machinery (ALL layers, built once)
__device__ __align__(256) __half g_T2hi[(size_t)NLAY * H * CL * 192];
__device__ __align__(256) __half g_T1hi[(size_t)NLAY * H * 64 * CL];

// ---------------- helpers ----------------
__device__ __forceinline__ void cpa16(void* dst, const void* src) {
    unsigned d = (unsigned)__cvta_generic_to_shared(dst);
    asm volatile("cp.async.cg.shared.global [%0], [%1], 16;" :: "r"(d), "l"(src));
}
__device__ __forceinline__ void ldsm4(uint32_t& r0, uint32_t& r1, uint32_t& r2,
                                      uint32_t& r3, const void* p) {
    uint32_t a = (uint32_t)__cvta_generic_to_shared(p);
    asm volatile("ldmatrix.sync.aligned.m8n8.x4.shared.b16 {%0,%1,%2,%3}, [%4];"
                 : "=r"(r0), "=r"(r1), "=r"(r2), "=r"(r3) : "r"(a));
}
__device__ __forceinline__ void ldsm4t(uint32_t& r0, uint32_t& r1, uint32_t& r2,
                                       uint32_t& r3, const void* p) {
    uint32_t a = (uint32_t)__cvta_generic_to_shared(p);
    asm volatile("ldmatrix.sync.aligned.m8n8.x4.trans.shared.b16 {%0,%1,%2,%3}, [%4];"
                 : "=r"(r0), "=r"(r1), "=r"(r2), "=r"(r3) : "r"(a));
}
__device__ __forceinline__ void mma_f16(float* d, const uint32_t* a,
                                        uint32_t b0, uint32_t b1) {
    asm volatile(
        "mma.sync.aligned.m16n8k16.row.col.f32.f16.f16.f32 "
        "{%0,%1,%2,%3}, {%4,%5,%6,%7}, {%8,%9}, {%0,%1,%2,%3};"
        : "+f"(d[0]), "+f"(d[1]), "+f"(d[2]), "+f"(d[3])
        : "r"(a[0]), "r"(a[1]), "r"(a[2]), "r"(a[3]), "r"(b0), "r"(b1));
}
__device__ __forceinline__ float gelu_f(float v) {
    return 0.5f * v * (1.0f + erff(v * 0.70710678118654752f));
}

// =====================================================================
// xsplit: (B,L,H) fp32 -> (B,H,L) fp16 (layer 0 only)
// =====================================================================
__global__ __launch_bounds__(256) void xsplit(const float* __restrict__ x) {
    __shared__ float tile[32][33];
    int b = blockIdx.z, h0 = blockIdx.x * 32, l0 = blockIdx.y * 32;
    int tx = threadIdx.x, ty = threadIdx.y;
#pragma unroll
    for (int j = 0; j < 32; j += 8)
        tile[ty + j][tx] = x[((size_t)b * LSEQ + l0 + ty + j) * H + h0 + tx];
    __syncthreads();
#pragma unroll
    for (int j = 0; j < 32; j += 8) {
        size_t o = ((size_t)(b * H + h0 + ty + j)) * LSEQ + l0 + tx;
        g_Uhi[o] = __float2half_rn(tile[tx][ty + j]);
    }
}

// =====================================================================
// tbuild: per-(h,layer) Toeplitz kernel, correction V, end-state E.
// =====================================================================
__global__ __launch_bounds__(256) void tbuild(
    const float* __restrict__ log_dt, const float* __restrict__ A_imag,
    const float* __restrict__ log_A_real, const float* __restrict__ Cp,
    const float* __restrict__ Dp)
{
    __shared__ float wr[CL + 1][32], wi[CL + 1][32];
    __shared__ float scfr[32], scfi[32], skern[CL];
    __shared__ float sD;
    int h = blockIdx.x;
    int layer = blockIdx.y;
    int t = threadIdx.x;
    __half* T2 = g_T2hi + (size_t)layer * H * CL * 192;
    __half* T1 = g_T1hi + (size_t)layer * H * 64 * CL;
    if (t == 0) sD = Dp[layer * H + h];
    if (t < 32) {
        int n = t;
        float dt = expf(log_dt[layer * H + h]);
        float Are = -expf(log_A_real[(layer * H + h) * N2 + n]);
        float Aim = A_imag[(layer * H + h) * N2 + n];
        float e1 = expf(Are * dt);
        float w1r = e1 * cosf(Aim * dt), w1i = e1 * sinf(Aim * dt);
        float nr = w1r - 1.0f, ni = w1i;
        float cr = Cp[((layer * H + h) * N2 + n) * 2 + 0];
        float ci = Cp[((layer * H + h) * N2 + n) * 2 + 1];
        float tr = cr * nr - ci * ni;
        float ti = cr * ni + ci * nr;
        float inv = 2.0f / (Are * Are + Aim * Aim);
        scfr[n] = (tr * Are + ti * Aim) * inv;
        scfi[n] = (ti * Are - tr * Aim) * inv;
        float pr = 1.0f, pi = 0.0f;
        for (int d = 0; d <= CL; d++) {
            wr[d][n] = pr; wi[d][n] = pi;
            float npr = pr * w1r - pi * w1i;
            float npi = pr * w1i + pi * w1r;
            pr = npr; pi = npi;
        }
    }
    __syncthreads();
    if (t < CL) {
        float acc = (t == 0) ? sD : 0.0f;
#pragma unroll 8
        for (int n = 0; n < 32; n++)
            acc += scfr[n] * wr[t][n] - scfi[n] * wi[t][n];
        skern[t] = acc;
    }
    __syncthreads();
    for (int idx = t; idx < CL * CL; idx += 256) {
        int n = idx >> 7, k = idx & 127;
        float v = (k <= n) ? skern[n - k] : 0.0f;
        T2[((size_t)h * CL + n) * 192 + k] = __float2half_rn(v);
    }
    for (int idx = t; idx < CL * 64; idx += 256) {
        int n = idx >> 6, e = idx & 63, ns = e >> 1;
        float cwr = scfr[ns] * wr[n + 1][ns] - scfi[ns] * wi[n + 1][ns];
        float cwi = scfr[ns] * wi[n + 1][ns] + scfi[ns] * wr[n + 1][ns];
        float v = (e & 1) ? -cwi : cwr;
        T2[((size_t)h * CL + n) * 192 + 128 + e] = __float2half_rn(v);
    }
    for (int idx = t; idx < 64 * CL; idx += 256) {
        int e = idx >> 7, j = idx & 127, ns = e >> 1;
        int d = CL - 1 - j;
        float v = (e & 1) ? wi[d][ns] : wr[d][ns];
        T1[((size_t)h * 64 + e) * CL + j] = __float2half_rn(v);
    }
}

// =====================================================================
// ssm_fused: block per h.
//  Phase 1: S_end[256x64] = Uhi @ T1^T  -> E smem -> prefix -> S smem.
//  Phase 2: for mt=0,1: Y[128x128] = [U | S]hi @ T2^T, GELU, store.
// smem: [0,36864) persistent S (256x72 halves);
//       [36864, +46080) pipeline region (phase1 3x15360 / phase2 3x12288,
//       E overlay 256x66 halves) -- total 82944 B.
// =====================================================================
#define FS_ROW   72u             /* halves per S row (144B, conflict-free) */
#define FS_BYTES 36864u
#define P1_BOFF  12288u
#define P1_STAGE 15360u
#define P2_BOFF  6144u
#define P2_STAGE 12288u
#define F_DSMEM  (FS_BYTES + 3 * P1_STAGE)   /* 82944 */

__global__ __launch_bounds__(256, 2) void ssm_fused(
    const float* __restrict__ log_dt, const float* __restrict__ A_imag,
    const float* __restrict__ log_A_real, int layer)
{
    extern __shared__ __align__(16) char dsm[];
    __half* Ssm = (__half*)dsm;                    // persistent S region
    char* pipe = dsm + FS_BYTES;                   // pipeline region

    int tid = threadIdx.x;
    int warp = tid >> 5, lane = tid & 31;
    int grp = lane >> 2, tq = lane & 3;
    int h = blockIdx.x;
    int lrow8 = (lane & 7) + (lane & 8);
    int khalf = (lane >> 4) * 16;

    // ---------------- Phase 1: end-state GEMM ----------------
    {
        int wm = warp * 32;
        int bb = tid >> 5, cc = tid & 31;
        const __half* aU = g_Uhi + ((size_t)(bb * H + h)) * LSEQ + cc * CL;
        const __half* bTh = g_T1hi + ((size_t)layer * H + h) * 64 * CL;

        float acc[2][8][4];
#pragma unroll
        for (int mi = 0; mi < 2; mi++)
#pragma unroll
            for (int ni = 0; ni < 8; ni++)
#pragma unroll
                for (int r = 0; r < 4; r++) acc[mi][ni][r] = 0.0f;

#define LOAD_P1(KT, S)                                                           \
        do {                                                                     \
            char* sb = pipe + (unsigned)(S) * P1_STAGE;                          \
            cpa16(sb + (unsigned)(tid * 48),      aU + (KT) * 16);               \
            cpa16(sb + (unsigned)(tid * 48 + 16), aU + (KT) * 16 + 8);           \
            if (tid < 128)                                                       \
                cpa16(sb + P1_BOFF + (unsigned)((tid >> 1) * 48 + (tid & 1) * 16),\
                      bTh + (size_t)(tid >> 1) * CL + (KT) * 16 + (tid & 1) * 8);\
            asm volatile("cp.async.commit_group;" ::: "memory");                 \
        } while (0)

        LOAD_P1(0, 0);
        LOAD_P1(1, 1);
        for (int kt = 0; kt < 8; kt++) {
            int s = kt - (kt / 3) * 3;
            if (kt + 2 < 8) asm volatile("cp.async.wait_group 1;" ::: "memory");
            else            asm volatile("cp.async.wait_group 0;" ::: "memory");
            __syncthreads();
            if (kt + 2 < 8) {
                int s2 = (kt + 2) - ((kt + 2) / 3) * 3;
                LOAD_P1(kt + 2, s2);
            }
            const char* sb = pipe + (unsigned)s * P1_STAGE;
            uint32_t ah[2][4];
#pragma unroll
            for (int mi = 0; mi < 2; mi++) {
                const char* pa = sb + (unsigned)((wm + mi * 16 + lrow8) * 48) + khalf;
                ldsm4(ah[mi][0], ah[mi][1], ah[mi][2], ah[mi][3], pa);
            }
            uint32_t bh[8][2];
#pragma unroll
            for (int p = 0; p < 4; p++) {
                const char* pb = sb + P1_BOFF + (unsigned)((p * 16 + lrow8) * 48) + khalf;
                ldsm4(bh[2 * p][0], bh[2 * p + 1][0], bh[2 * p][1], bh[2 * p + 1][1], pb);
            }
#pragma unroll
            for (int ni = 0; ni < 8; ni++)
#pragma unroll
                for (int mi = 0; mi < 2; mi++)
                    mma_f16(acc[mi][ni], ah[mi], bh[ni][0], bh[ni][1]);
        }
        __syncthreads();   // pipeline done; overlay E

        __half (*E)[66] = (__half(*)[66])pipe;
#pragma unroll
        for (int mi = 0; mi < 2; mi++) {
            int r = wm + mi * 16 + grp;
#pragma unroll
            for (int ni = 0; ni < 8; ni++) {
                int cidx = ni * 8 + tq * 2;
                *(__half2*)&E[r][cidx]     = __floats2half2_rn(acc[mi][ni][0], acc[mi][ni][1]);
                *(__half2*)&E[r + 8][cidx] = __floats2half2_rn(acc[mi][ni][2], acc[mi][ni][3]);
            }
        }
        __syncthreads();

        // prefix: thread = (b, n) complex chain over 32 chunks -> Ssm
        int b = tid >> 5, n = tid & 31;
        float dt = expf(log_dt[layer * H + h]);
        float Are = -expf(log_A_real[(layer * H + h) * N2 + n]);
        float Aim = A_imag[(layer * H + h) * N2 + n];
        float e = expf(Are * dt * (float)CL);
        float Wr = e * cosf(Aim * dt * (float)CL);
        float Wi = e * sinf(Aim * dt * (float)CL);
        float Ir = 0.0f, Ii = 0.0f;
#pragma unroll 4
        for (int c = 0; c < NC; c++) {
            *(__half2*)&Ssm[(unsigned)(b * 32 + c) * FS_ROW + 2 * n] =
                __floats2half2_rn(Ir, Ii);
            float er = __half2float(E[b * 32 + c][2 * n]);
            float ei = __half2float(E[b * 32 + c][2 * n + 1]);
            float nr = fmaf(Wr, Ir, fmaf(-Wi, Ii, er));
            float ni = fmaf(Wi, Ir, fmaf( Wr, Ii, ei));
            Ir = nr; Ii = ni;
        }
        __syncthreads();
    }

    // ---------------- Phase 2: Toeplitz GEMM (2 m-tiles) ----------------
    {
        int wm = (warp >> 1) * 32, wn = (warp & 1) * 64;
        int mloc = tid >> 1, ch = tid & 1;
        const __half* bTh = g_T2hi + ((size_t)layer * H + h) * CL * 192;

        for (int mt = 0; mt < 2; mt++) {
            int m = mt * 128 + mloc;
            int bb = m >> 5, cc = m & 31;
            const __half* aUh = g_Uhi + ((size_t)(bb * H + h)) * LSEQ + cc * CL;

            float acc[2][8][4];
#pragma unroll
            for (int mi = 0; mi < 2; mi++)
#pragma unroll
                for (int ni = 0; ni < 8; ni++)
#pragma unroll
                    for (int r = 0; r < 4; r++) acc[mi][ni][r] = 0.0f;

#define LOAD_P2(KT, S)                                                           \
            do {                                                                 \
                char* sb = pipe + (unsigned)(S) * P2_STAGE;                      \
                int k0 = (KT) * 16 + ch * 8;                                     \
                if (k0 < 128)                                                    \
                    cpa16(sb + (unsigned)(mloc * 48 + ch * 16), aUh + k0);       \
                cpa16(sb + P2_BOFF + (unsigned)(mloc * 48 + ch * 16),            \
                      bTh + (size_t)mloc * 192 + k0);                            \
                asm volatile("cp.async.commit_group;" ::: "memory");             \
            } while (0)

            LOAD_P2(0, 0);
            LOAD_P2(1, 1);
            for (int kt = 0; kt < 12; kt++) {
                int s = kt - (kt / 3) * 3;
                if (kt + 2 < 12) asm volatile("cp.async.wait_group 1;" ::: "memory");
                else             asm volatile("cp.async.wait_group 0;" ::: "memory");
                __syncthreads();
                if (kt + 2 < 12) {
                    int s2 = (kt + 2) - ((kt + 2) / 3) * 3;
                    LOAD_P2(kt + 2, s2);
                }
                const char* sb = pipe + (unsigned)s * P2_STAGE;
                uint32_t ah[2][4];
                if (kt < 8) {
#pragma unroll
                    for (int mi = 0; mi < 2; mi++) {
                        const char* pa = sb + (unsigned)((wm + mi * 16 + lrow8) * 48) + khalf;
                        ldsm4(ah[mi][0], ah[mi][1], ah[mi][2], ah[mi][3], pa);
                    }
                } else {
#pragma unroll
                    for (int mi = 0; mi < 2; mi++) {
                        const char* pa = (const char*)Ssm
                            + (unsigned)((mt * 128 + wm + mi * 16 + lrow8) * 144
                                         + (kt - 8) * 32) + khalf;
                        ldsm4(ah[mi][0], ah[mi][1], ah[mi][2], ah[mi][3], pa);
                    }
                }
                uint32_t bh[8][2];
#pragma unroll
                for (int p = 0; p < 4; p++) {
                    const char* pb = sb + P2_BOFF
                        + (unsigned)((wn + p * 16 + lrow8) * 48) + khalf;
                    ldsm4(bh[2 * p][0], bh[2 * p + 1][0], bh[2 * p][1],
                          bh[2 * p + 1][1], pb);
                }
#pragma unroll
                for (int ni = 0; ni < 8; ni++)
#pragma unroll
                    for (int mi = 0; mi < 2; mi++)
                        mma_f16(acc[mi][ni], ah[mi], bh[ni][0], bh[ni][1]);
            }
            // epilogue: GELU + fp16 store (B,H,L)
#pragma unroll
            for (int mi = 0; mi < 2; mi++) {
                int r = mt * 128 + wm + mi * 16 + grp;
                int b0 = r >> 5, c0 = r & 31;
                int r1 = r + 8;
                int b1 = r1 >> 5, c1 = r1 & 31;
                __half* y0 = g_Yt16 + ((size_t)(b0 * H + h)) * LSEQ + c0 * CL;
                __half* y1 = g_Yt16 + ((size_t)(b1 * H + h)) * LSEQ + c1 * CL;
#pragma unroll
                for (int ni = 0; ni < 8; ni++) {
                    int n = wn + ni * 8 + tq * 2;
                    *(__half2*)(y0 + n) = __floats2half2_rn(gelu_f(acc[mi][ni][0]),
                                                            gelu_f(acc[mi][ni][1]));
                    *(__half2*)(y1 + n) = __floats2half2_rn(gelu_f(acc[mi][ni][2]),
                                                            gelu_f(acc[mi][ni][3]));
                }
            }
            __syncthreads();
        }
    }
}

// =====================================================================
// W prep: interleave rows, fp16.
// =====================================================================
__global__ __launch_bounds__(256) void w_prep(const float* __restrict__ W,
                                              const float* __restrict__ bp) {
    size_t i = (size_t)blockIdx.x * 256 + threadIdx.x;
    int col = (int)(i % H);
    int k   = (int)((i / H) % (2 * H));
    int l   = (int)(i / ((size_t)H * 2 * H));
    int orig = (k >> 1) + (k & 1) * H;
    float v = W[((size_t)l * 2 * H + orig) * H + col];
    g_Whi[i] = __float2half_rn(v);
    if (i < NLAY * 2 * H) {
        int kk = (int)(i % (2 * H));
        int ll = (int)(i / (2 * H));
        int og = (kk >> 1) + (kk & 1) * H;
        g_bint[i] = bp[ll * 2 * H + og];
    }
}

// =====================================================================
// conv GEMM + fused GLU: 1-term, A via ldmatrix.x4.trans from (B,H,L).
// =====================================================================
#define C_BOFF  4608u
#define C_STAGE 10752u
#define C_DSMEM (3 * C_STAGE)   /* 32256 */

__global__ __launch_bounds__(256, 2) void conv_gemm(int layer)
{
    extern __shared__ __align__(16) char dsm[];
    int tid = threadIdx.x;
    int warp = tid >> 5, lane = tid & 31;
    int grp = lane >> 2, tq = lane & 3;
    int n0 = blockIdx.x * 128, m0 = blockIdx.y * 128;
    int bB = m0 >> 12;
    int l0 = m0 & (LSEQ - 1);

    const __half* Wh = g_Whi + (size_t)layer * 2 * H * H;

    int wm = (warp >> 1) * 32, wn = (warp & 1) * 64;
    int lrow8 = (lane & 7) + (lane & 8);
    int khalf = (lane >> 4) * 16;
    int ktr = ((lane >> 4) & 1) * 8 + (lane & 7);
    int mby = ((lane >> 3) & 1) * 16;

    float acc[2][8][4];
#pragma unroll
    for (int mi = 0; mi < 2; mi++)
#pragma unroll
        for (int ni = 0; ni < 8; ni++)
#pragma unroll
            for (int r = 0; r < 4; r++) acc[mi][ni][r] = 0.0f;

    int fa_r = tid >> 4, fa_c = tid & 15;
    int fb_r = tid >> 1, fb_c = tid & 1;

#define LOAD_C(KT, S)                                                            \
    do {                                                                         \
        char* sb = dsm + (unsigned)(S) * C_STAGE;                                \
        cpa16(sb + (unsigned)(fa_r * 272 + fa_c * 16),                           \
              g_Yt16 + ((size_t)(bB * H + (KT) * 16 + fa_r)) * LSEQ + l0 + fa_c * 8); \
        cpa16(sb + C_BOFF + (unsigned)(fb_r * 48 + fb_c * 16),                   \
              Wh + (size_t)(n0 + fb_r) * H + (KT) * 16 + fb_c * 8);              \
        asm volatile("cp.async.commit_group;" ::: "memory");                     \
    } while (0)

    LOAD_C(0, 0);
    LOAD_C(1, 1);

    const int NKT = H / 16;   // 32
    for (int kt = 0; kt < NKT; kt++) {
        int s = kt - (kt / 3) * 3;
        if (kt + 2 < NKT) asm volatile("cp.async.wait_group 1;" ::: "memory");
        else              asm volatile("cp.async.wait_group 0;" ::: "memory");
        __syncthreads();
        if (kt + 2 < NKT) {
            int s2 = (kt + 2) - ((kt + 2) / 3) * 3;
            LOAD_C(kt + 2, s2);
        }
        const char* sb = dsm + (unsigned)s * C_STAGE;
        uint32_t ah[2][4];
#pragma unroll
        for (int mi = 0; mi < 2; mi++) {
            const char* pa = sb + (unsigned)(ktr * 272 + (wm + mi * 16) * 2 + mby);
            ldsm4t(ah[mi][0], ah[mi][1], ah[mi][2], ah[mi][3], pa);
        }
        uint32_t bh[8][2];
#pragma unroll
        for (int p = 0; p < 4; p++) {
            const char* pb = sb + C_BOFF + (unsigned)((wn + p * 16 + lrow8) * 48) + khalf;
            ldsm4(bh[2 * p][0], bh[2 * p + 1][0], bh[2 * p][1], bh[2 * p + 1][1], pb);
        }
#pragma unroll
        for (int ni = 0; ni < 8; ni++)
#pragma unroll
            for (int mi = 0; mi < 2; mi++)
                mma_f16(acc[mi][ni], ah[mi], bh[ni][0], bh[ni][1]);
    }
#pragma unroll
    for (int mi = 0; mi < 2; mi++)
#pragma unroll
        for (int ni = 0; ni < 8; ni++) {
            int r  = m0 + wm + mi * 16 + grp;
            int cb = wn + ni * 8 + tq * 2;
            float ba = g_bint[layer * 2 * H + n0 + cb];
            float bg = g_bint[layer * 2 * H + n0 + cb + 1];
            float a0 = acc[mi][ni][0] + ba, gg0 = acc[mi][ni][1] + bg;
            float a1 = acc[mi][ni][2] + ba, gg1 = acc[mi][ni][3] + bg;
            int hidx = (n0 + cb) >> 1;
            g_Zh[(size_t)r * H + hidx]       = __float2half_rn(a0 / (1.0f + expf(-gg0)));
            g_Zh[(size_t)(r + 8) * H + hidx] = __float2half_rn(a1 / (1.0f + expf(-gg1)));
        }
}

// =====================================================================
// res_ln_final: residual (fp16 xin) + LN -> fp32 out. warp per row.
// =====================================================================
__global__ __launch_bounds__(128) void res_ln_final(
    const __half* __restrict__ xin, float* __restrict__ xout,
    const float* __restrict__ gamma, const float* __restrict__ beta, int layer)
{
    int row  = blockIdx.x * 4 + (threadIdx.x >> 5);
    int lane = threadIdx.x & 31;
    const __half2* zh = (const __half2*)(g_Zh + (size_t)row * H);
    const __half2* xh = (const __half2*)(xin + (size_t)row * H);
    float4* o4       = (float4*)(xout + (size_t)row * H);
    const float4* g4 = (const float4*)(gamma + layer * H);
    const float4* e4 = (const float4*)(beta + layer * H);

    float4 v[4];
    float s = 0.0f, s2 = 0.0f;
#pragma unroll
    for (int j = 0; j < 4; j++) {
        __half2 p0 = zh[(j * 32 + lane) * 2];
        __half2 p1 = zh[(j * 32 + lane) * 2 + 1];
        __half2 x0 = xh[(j * 32 + lane) * 2];
        __half2 x1 = xh[(j * 32 + lane) * 2 + 1];
        float4 vv;
        vv.x = __low2float(p0) + __low2float(x0);
        vv.y = __high2float(p0) + __high2float(x0);
        vv.z = __low2float(p1) + __low2float(x1);
        vv.w = __high2float(p1) + __high2float(x1);
        v[j] = vv;
        s += vv.x + vv.y + vv.z + vv.w;
        s2 = fmaf(vv.x, vv.x, s2); s2 = fmaf(vv.y, vv.y, s2);
        s2 = fmaf(vv.z, vv.z, s2); s2 = fmaf(vv.w, vv.w, s2);
    }
#pragma unroll
    for (int o = 16; o; o >>= 1) {
        s  += __shfl_xor_sync(0xffffffffu, s, o);
        s2 += __shfl_xor_sync(0xffffffffu, s2, o);
    }
    float mu = s * (1.0f / H);
    float rs = rsqrtf(s2 * (1.0f / H) - mu * mu + LN_EPS);
#pragma unroll
    for (int j = 0; j < 4; j++) {
        float4 ga = g4[j * 32 + lane];
        float4 be = e4[j * 32 + lane];
        float4 vv = v[j], o;
        o.x = (vv.x - mu) * rs * ga.x + be.x;
        o.y = (vv.y - mu) * rs * ga.y + be.y;
        o.z = (vv.z - mu) * rs * ga.z + be.z;
        o.w = (vv.w - mu) * rs * ga.w + be.w;
        o4[j * 32 + lane] = o;
    }
}

// =====================================================================
// res_lnT (layers 0..2): residual + LN; fp16 xout (B,L,H) and
// transposed fp16 U plane (B,H,L). IN32: layer 0 reads fp32 x.
// =====================================================================
#define RL_SMEM (32 * 513 * 4)   /* 65664 */
template <int IN32>
__global__ __launch_bounds__(256) void res_lnT(
    const float* __restrict__ xin32, const __half* __restrict__ xin16,
    __half* __restrict__ xout16,
    const float* __restrict__ gamma, const float* __restrict__ beta, int layer)
{
    extern __shared__ float sv[];    // [32][513]
    int warp = threadIdx.x >> 5, lane = threadIdx.x & 31;
    int row0 = blockIdx.x * 32;
    int b = row0 >> 12;
    int l0 = row0 & (LSEQ - 1);
    const float4* g4 = (const float4*)(gamma + layer * H);
    const float4* e4 = (const float4*)(beta + layer * H);

#pragma unroll
    for (int i = 0; i < 4; i++) {
        int lr = warp * 4 + i;
        int row = row0 + lr;
        const __half2* zh = (const __half2*)(g_Zh + (size_t)row * H);
        __half2* oh = (__half2*)(xout16 + (size_t)row * H);
        float4 v[4];
        float s = 0.0f, s2 = 0.0f;
#pragma unroll
        for (int j = 0; j < 4; j++) {
            __half2 p0 = zh[(j * 32 + lane) * 2];
            __half2 p1 = zh[(j * 32 + lane) * 2 + 1];
            float4 xv;
            if (IN32) {
                xv = ((const float4*)(xin32 + (size_t)row * H))[j * 32 + lane];
            } else {
                const __half2* xh = (const __half2*)(xin16 + (size_t)row * H);
                __half2 x0 = xh[(j * 32 + lane) * 2];
                __half2 x1 = xh[(j * 32 + lane) * 2 + 1];
                xv.x = __low2float(x0); xv.y = __high2float(x0);
                xv.z = __low2float(x1); xv.w = __high2float(x1);
            }
            float4 vv;
            vv.x = __low2float(p0)  + xv.x; vv.y = __high2float(p0) + xv.y;
            vv.z = __low2float(p1)  + xv.z; vv.w = __high2float(p1) + xv.w;
            v[j] = vv;
            s += vv.x + vv.y + vv.z + vv.w;
            s2 = fmaf(vv.x, vv.x, s2); s2 = fmaf(vv.y, vv.y, s2);
            s2 = fmaf(vv.z, vv.z, s2); s2 = fmaf(vv.w, vv.w, s2);
        }
#pragma unroll
        for (int o = 16; o; o >>= 1) {
            s  += __shfl_xor_sync(0xffffffffu, s, o);
            s2 += __shfl_xor_sync(0xffffffffu, s2, o);
        }
        float mu = s * (1.0f / H);
        float rs = rsqrtf(s2 * (1.0f / H) - mu * mu + LN_EPS);
#pragma unroll
        for (int j = 0; j < 4; j++) {
            float4 ga = g4[j * 32 + lane];
            float4 be = e4[j * 32 + lane];
            float4 vv = v[j], o;
            o.x = (vv.x - mu) * rs * ga.x + be.x;
            o.y = (vv.y - mu) * rs * ga.y + be.y;
            o.z = (vv.z - mu) * rs * ga.z + be.z;
            o.w = (vv.w - mu) * rs * ga.w + be.w;
            oh[(j * 32 + lane) * 2]     = __floats2half2_rn(o.x, o.y);
            oh[(j * 32 + lane) * 2 + 1] = __floats2half2_rn(o.z, o.w);
            int hh = (j * 32 + lane) * 4;
            sv[lr * 513 + hh + 0] = o.x;
            sv[lr * 513 + hh + 1] = o.y;
            sv[lr * 513 + hh + 2] = o.z;
            sv[lr * 513 + hh + 3] = o.w;
        }
    }
    __syncthreads();
#pragma unroll 4
    for (int it = 0; it < 64; it++) {
        int h = it * 8 + warp;
        float v = sv[lane * 513 + h];
        g_Uhi[((size_t)(b * H + h)) * LSEQ + l0 + lane] = __float2half_rn(v);
    }
}

// ================= launcher =================
extern "C" void kernel_launch(void* const* d_in, const int* in_sizes, int n_in,
                              void* d_out, int out_size)
{
    const float* x          = (const float*)d_in[0];
    const float* log_dt     = (const float*)d_in[1];
    const float* A_imag     = (const float*)d_in[2];
    const float* log_A_real = (const float*)d_in[3];
    const float* C          = (const float*)d_in[4];
    const float* D          = (const float*)d_in[5];
    const float* W          = (const float*)d_in[6];
    const float* bconv      = (const float*)d_in[7];
    const float* gamma      = (const float*)d_in[8];
    const float* beta       = (const float*)d_in[9];
    float* out = (float*)d_out;

    cudaFuncSetAttribute(conv_gemm, cudaFuncAttributeMaxDynamicSharedMemorySize,
                         C_DSMEM);
    cudaFuncSetAttribute(ssm_fused, cudaFuncAttributeMaxDynamicSharedMemorySize,
                         F_DSMEM);
    cudaFuncSetAttribute(res_lnT<0>, cudaFuncAttributeMaxDynamicSharedMemorySize,
                         RL_SMEM);
    cudaFuncSetAttribute(res_lnT<1>, cudaFuncAttributeMaxDynamicSharedMemorySize,
                         RL_SMEM);

    __half* pA; cudaGetSymbolAddress((void**)&pA, g_x16A);
    __half* pB; cudaGetSymbolAddress((void**)&pB, g_x16B);

    w_prep<<<(NLAY * 2 * H * H) / 256, 256>>>(W, bconv);
    tbuild<<<dim3(H, NLAY), 256>>>(log_dt, A_imag, log_A_real, C, D);

    dim3 tb(32, 8);
    xsplit<<<dim3(H / 32, LSEQ / 32, BSZ), tb>>>(x);   // layer-0 U plane

    for (int i = 0; i < NLAY; i++) {
        ssm_fused<<<H, 256, F_DSMEM>>>(log_dt, A_imag, log_A_real, i);
        conv_gemm<<<dim3(2 * H / 128, MROWS / 128), 256, C_DSMEM>>>(i);
        if (i == 0)
            res_lnT<1><<<MROWS / 32, 256, RL_SMEM>>>(x, nullptr, pA,
                                                     gamma, beta, 0);
        else if (i == 1)
            res_lnT<0><<<MROWS / 32, 256, RL_SMEM>>>(nullptr, pA, pB,
                                                     gamma, beta, 1);
        else if (i == 2)
            res_lnT<0><<<MROWS / 32, 256, RL_SMEM>>>(nullptr, pB, pA,
                                                     gamma, beta, 2);
        else
            res_ln_final<<<MROWS / 4, 128>>>(pA, out, gamma, beta, 3);
    }
}

// round 17
// speedup vs baseline: 1.0256x; 1.0256x over previous
#include <cuda_runtime.h>
#include <cuda_fp16.h>
#include <cstdint>

#define H     512
#define NLAY  4
#define N2    32
#define BSZ   8
#define LSEQ  4096
#define MROWS (BSZ * LSEQ)      /* 32768 */
#define NC    32                /* chunks per sequence */
#define CL    (LSEQ / NC)       /* 128 */
#define NINST (BSZ * NC)        /* 256 instances per h */
#define LN_EPS 1e-5f

// ---- static scratch ----
__device__ __align__(256) __half g_x16A[(size_t)MROWS * H];   // residual fp16 ping
__device__ __align__(256) __half g_x16B[(size_t)MROWS * H];   // residual fp16 pong
__device__ __align__(256) __half g_Uhi [(size_t)MROWS * H];   // u (B,H,L)
__device__ __align__(256) __half g_Yt16[(size_t)MROWS * H];   // gelu(y) (B,H,L)
__device__ __align__(256) __half g_Whi[(size_t)NLAY * 2 * H * H];
__device__ __align__(256) float g_bint[NLAY * 2 * H];
__device__ __align__(256) __half g_Zh[(size_t)MROWS * H];     // GLU out (B,L,H)
// Toeplitz machinery (ALL layers, built once)
__device__ __align__(256) __half g_T2hi[(size_t)NLAY * H * CL * 192];
__device__ __align__(256) __half g_T1hi[(size_t)NLAY * H * 64 * CL];
__device__ __align__(256) __half g_Shi[(size_t)H * NINST * 64]; // init states

// ---------------- helpers ----------------
__device__ __forceinline__ void cpa16(void* dst, const void* src) {
    unsigned d = (unsigned)__cvta_generic_to_shared(dst);
    asm volatile("cp.async.cg.shared.global [%0], [%1], 16;" :: "r"(d), "l"(src));
}
__device__ __forceinline__ void ldsm4(uint32_t& r0, uint32_t& r1, uint32_t& r2,
                                      uint32_t& r3, const void* p) {
    uint32_t a = (uint32_t)__cvta_generic_to_shared(p);
    asm volatile("ldmatrix.sync.aligned.m8n8.x4.shared.b16 {%0,%1,%2,%3}, [%4];"
                 : "=r"(r0), "=r"(r1), "=r"(r2), "=r"(r3) : "r"(a));
}
__device__ __forceinline__ void ldsm4t(uint32_t& r0, uint32_t& r1, uint32_t& r2,
                                       uint32_t& r3, const void* p) {
    uint32_t a = (uint32_t)__cvta_generic_to_shared(p);
    asm volatile("ldmatrix.sync.aligned.m8n8.x4.trans.shared.b16 {%0,%1,%2,%3}, [%4];"
                 : "=r"(r0), "=r"(r1), "=r"(r2), "=r"(r3) : "r"(a));
}
__device__ __forceinline__ void mma_f16(float* d, const uint32_t* a,
                                        uint32_t b0, uint32_t b1) {
    asm volatile(
        "mma.sync.aligned.m16n8k16.row.col.f32.f16.f16.f32 "
        "{%0,%1,%2,%3}, {%4,%5,%6,%7}, {%8,%9}, {%0,%1,%2,%3};"
        : "+f"(d[0]), "+f"(d[1]), "+f"(d[2]), "+f"(d[3])
        : "r"(a[0]), "r"(a[1]), "r"(a[2]), "r"(a[3]), "r"(b0), "r"(b1));
}
__device__ __forceinline__ float gelu_f(float v) {
    return 0.5f * v * (1.0f + erff(v * 0.70710678118654752f));
}

// =====================================================================
// xsplit: (B,L,H) fp32 -> (B,H,L) fp16 (layer 0 only)
// =====================================================================
__global__ __launch_bounds__(256) void xsplit(const float* __restrict__ x) {
    __shared__ float tile[32][33];
    int b = blockIdx.z, h0 = blockIdx.x * 32, l0 = blockIdx.y * 32;
    int tx = threadIdx.x, ty = threadIdx.y;
#pragma unroll
    for (int j = 0; j < 32; j += 8)
        tile[ty + j][tx] = x[((size_t)b * LSEQ + l0 + ty + j) * H + h0 + tx];
    __syncthreads();
#pragma unroll
    for (int j = 0; j < 32; j += 8) {
        size_t o = ((size_t)(b * H + h0 + ty + j)) * LSEQ + l0 + tx;
        g_Uhi[o] = __float2half_rn(tile[tx][ty + j]);
    }
}

// =====================================================================
// tbuild: per-(h,layer) Toeplitz kernel, correction V, end-state E.
// =====================================================================
__global__ __launch_bounds__(256) void tbuild(
    const float* __restrict__ log_dt, const float* __restrict__ A_imag,
    const float* __restrict__ log_A_real, const float* __restrict__ Cp,
    const float* __restrict__ Dp)
{
    __shared__ float wr[CL + 1][32], wi[CL + 1][32];
    __shared__ float scfr[32], scfi[32], skern[CL];
    __shared__ float sD;
    int h = blockIdx.x;
    int layer = blockIdx.y;
    int t = threadIdx.x;
    __half* T2 = g_T2hi + (size_t)layer * H * CL * 192;
    __half* T1 = g_T1hi + (size_t)layer * H * 64 * CL;
    if (t == 0) sD = Dp[layer * H + h];
    if (t < 32) {
        int n = t;
        float dt = expf(log_dt[layer * H + h]);
        float Are = -expf(log_A_real[(layer * H + h) * N2 + n]);
        float Aim = A_imag[(layer * H + h) * N2 + n];
        float e1 = expf(Are * dt);
        float w1r = e1 * cosf(Aim * dt), w1i = e1 * sinf(Aim * dt);
        float nr = w1r - 1.0f, ni = w1i;
        float cr = Cp[((layer * H + h) * N2 + n) * 2 + 0];
        float ci = Cp[((layer * H + h) * N2 + n) * 2 + 1];
        float tr = cr * nr - ci * ni;
        float ti = cr * ni + ci * nr;
        float inv = 2.0f / (Are * Are + Aim * Aim);
        scfr[n] = (tr * Are + ti * Aim) * inv;
        scfi[n] = (ti * Are - tr * Aim) * inv;
        float pr = 1.0f, pi = 0.0f;
        for (int d = 0; d <= CL; d++) {
            wr[d][n] = pr; wi[d][n] = pi;
            float npr = pr * w1r - pi * w1i;
            float npi = pr * w1i + pi * w1r;
            pr = npr; pi = npi;
        }
    }
    __syncthreads();
    if (t < CL) {
        float acc = (t == 0) ? sD : 0.0f;
#pragma unroll 8
        for (int n = 0; n < 32; n++)
            acc += scfr[n] * wr[t][n] - scfi[n] * wi[t][n];
        skern[t] = acc;
    }
    __syncthreads();
    for (int idx = t; idx < CL * CL; idx += 256) {
        int n = idx >> 7, k = idx & 127;
        float v = (k <= n) ? skern[n - k] : 0.0f;
        T2[((size_t)h * CL + n) * 192 + k] = __float2half_rn(v);
    }
    for (int idx = t; idx < CL * 64; idx += 256) {
        int n = idx >> 6, e = idx & 63, ns = e >> 1;
        float cwr = scfr[ns] * wr[n + 1][ns] - scfi[ns] * wi[n + 1][ns];
        float cwi = scfr[ns] * wi[n + 1][ns] + scfi[ns] * wr[n + 1][ns];
        float v = (e & 1) ? -cwi : cwr;
        T2[((size_t)h * CL + n) * 192 + 128 + e] = __float2half_rn(v);
    }
    for (int idx = t; idx < 64 * CL; idx += 256) {
        int e = idx >> 7, j = idx & 127, ns = e >> 1;
        int d = CL - 1 - j;
        float v = (e & 1) ? wi[d][ns] : wr[d][ns];
        T1[((size_t)h * 64 + e) * CL + j] = __float2half_rn(v);
    }
}

// =====================================================================
// gemm_endpre: per h, S_end[256 x 64] = Uhi @ B1hi^T, then in-block
// prefix over chunks -> g_Shi. grid (H), 256 threads.
// =====================================================================
#define EP_BOFF  12288u
#define EP_STAGE 15360u
#define EP_DSMEM 46080u

__global__ __launch_bounds__(256, 2) void gemm_endpre(
    const float* __restrict__ log_dt, const float* __restrict__ A_imag,
    const float* __restrict__ log_A_real, int layer)
{
    extern __shared__ __align__(16) char dsmP[];
    int tid = threadIdx.x;
    int warp = tid >> 5, lane = tid & 31;
    int grp = lane >> 2, tq = lane & 3;
    int h = blockIdx.x;
    int wm = warp * 32;
    int lrow8 = (lane & 7) + (lane & 8);
    int khalf = (lane >> 4) * 16;

    int bb = tid >> 5, cc = tid & 31;
    const __half* aU = g_Uhi + ((size_t)(bb * H + h)) * LSEQ + cc * CL;
    const __half* bTh = g_T1hi + ((size_t)layer * H + h) * 64 * CL;

    float acc[2][8][4];
#pragma unroll
    for (int mi = 0; mi < 2; mi++)
#pragma unroll
        for (int ni = 0; ni < 8; ni++)
#pragma unroll
            for (int r = 0; r < 4; r++) acc[mi][ni][r] = 0.0f;

#define LOAD_EP(KT, S)                                                           \
    do {                                                                         \
        char* sb = dsmP + (unsigned)(S) * EP_STAGE;                              \
        cpa16(sb + (unsigned)(tid * 48),      aU + (KT) * 16);                   \
        cpa16(sb + (unsigned)(tid * 48 + 16), aU + (KT) * 16 + 8);               \
        if (tid < 128)                                                           \
            cpa16(sb + EP_BOFF + (unsigned)((tid >> 1) * 48 + (tid & 1) * 16),   \
                  bTh + (size_t)(tid >> 1) * CL + (KT) * 16 + (tid & 1) * 8);    \
        asm volatile("cp.async.commit_group;" ::: "memory");                     \
    } while (0)

    LOAD_EP(0, 0);
    LOAD_EP(1, 1);
    const int NKT = 8;
    for (int kt = 0; kt < NKT; kt++) {
        int s = kt - (kt / 3) * 3;
        if (kt + 2 < NKT) asm volatile("cp.async.wait_group 1;" ::: "memory");
        else              asm volatile("cp.async.wait_group 0;" ::: "memory");
        __syncthreads();
        if (kt + 2 < NKT) {
            int s2 = (kt + 2) - ((kt + 2) / 3) * 3;
            LOAD_EP(kt + 2, s2);
        }
        const char* sb = dsmP + (unsigned)s * EP_STAGE;
        uint32_t ah[2][4];
#pragma unroll
        for (int mi = 0; mi < 2; mi++) {
            const char* pa = sb + (unsigned)((wm + mi * 16 + lrow8) * 48) + khalf;
            ldsm4(ah[mi][0], ah[mi][1], ah[mi][2], ah[mi][3], pa);
        }
        uint32_t bh[8][2];
#pragma unroll
        for (int p = 0; p < 4; p++) {
            const char* pb = sb + EP_BOFF + (unsigned)((p * 16 + lrow8) * 48) + khalf;
            ldsm4(bh[2 * p][0], bh[2 * p + 1][0], bh[2 * p][1], bh[2 * p + 1][1], pb);
        }
#pragma unroll
        for (int ni = 0; ni < 8; ni++)
#pragma unroll
            for (int mi = 0; mi < 2; mi++)
                mma_f16(acc[mi][ni], ah[mi], bh[ni][0], bh[ni][1]);
    }
    __syncthreads();   // done with pipeline smem; overlay E

    __half (*E)[66] = (__half(*)[66])dsmP;
#pragma unroll
    for (int mi = 0; mi < 2; mi++) {
        int r = wm + mi * 16 + grp;
#pragma unroll
        for (int ni = 0; ni < 8; ni++) {
            int cidx = ni * 8 + tq * 2;
            *(__half2*)&E[r][cidx]     = __floats2half2_rn(acc[mi][ni][0], acc[mi][ni][1]);
            *(__half2*)&E[r + 8][cidx] = __floats2half2_rn(acc[mi][ni][2], acc[mi][ni][3]);
        }
    }
    __syncthreads();

    // prefix: thread = (b, n) complex chain over 32 chunks
    {
        int b = tid >> 5, n = tid & 31;
        float dt = expf(log_dt[layer * H + h]);
        float Are = -expf(log_A_real[(layer * H + h) * N2 + n]);
        float Aim = A_imag[(layer * H + h) * N2 + n];
        float e = expf(Are * dt * (float)CL);
        float Wr = e * cosf(Aim * dt * (float)CL);
        float Wi = e * sinf(Aim * dt * (float)CL);
        float Ir = 0.0f, Ii = 0.0f;
        __half* Sp = g_Shi + ((size_t)h * NINST + b * 32) * 64 + 2 * n;
#pragma unroll 4
        for (int c = 0; c < NC; c++) {
            *(__half2*)(Sp + (size_t)c * 64) = __floats2half2_rn(Ir, Ii);
            float er = __half2float(E[b * 32 + c][2 * n]);
            float ei = __half2float(E[b * 32 + c][2 * n + 1]);
            float nr = fmaf(Wr, Ir, fmaf(-Wi, Ii, er));
            float ni = fmaf(Wi, Ir, fmaf( Wr, Ii, ei));
            Ir = nr; Ii = ni;
        }
    }
}

// =====================================================================
// gemm_toep: per h, Y[NINST x 128] = [U|Sinit]hi @ B2hi^T. 1-term.
// Epilogue: GELU + fp16 store (B,H,L).
// =====================================================================
#define T_BOFF  6144u
#define T_STAGE 12288u
#define T_DSMEM (3 * T_STAGE)   /* 36864 */

__global__ __launch_bounds__(256, 2) void gemm_toep(int layer)
{
    extern __shared__ __align__(16) char dsmT[];
    int tid = threadIdx.x;
    int warp = tid >> 5, lane = tid & 31;
    int grp = lane >> 2, tq = lane & 3;
    int mt = blockIdx.x, h = blockIdx.y;
    int wm = (warp >> 1) * 32, wn = (warp & 1) * 64;
    int lrow8 = (lane & 7) + (lane & 8);
    int khalf = (lane >> 4) * 16;

    int mloc = tid >> 1, ch = tid & 1;
    int m = mt * 128 + mloc;
    int bb = m >> 5, cc = m & 31;
    const __half* aUh = g_Uhi + ((size_t)(bb * H + h)) * LSEQ + cc * CL;
    const __half* aSh = g_Shi + ((size_t)h * NINST + m) * 64;
    const __half* bTh = g_T2hi + ((size_t)layer * H + h) * CL * 192;

    float acc[2][8][4];
#pragma unroll
    for (int mi = 0; mi < 2; mi++)
#pragma unroll
        for (int ni = 0; ni < 8; ni++)
#pragma unroll
            for (int r = 0; r < 4; r++) acc[mi][ni][r] = 0.0f;

#define LOAD_T(KT, S)                                                            \
    do {                                                                         \
        char* sb = dsmT + (unsigned)(S) * T_STAGE;                               \
        int k0 = (KT) * 16 + ch * 8;                                             \
        const __half* sh = (k0 < 128) ? aUh + k0 : aSh + (k0 - 128);             \
        cpa16(sb + (unsigned)(mloc * 48 + ch * 16), sh);                         \
        cpa16(sb + T_BOFF + (unsigned)(mloc * 48 + ch * 16),                     \
              bTh + (size_t)mloc * 192 + k0);                                    \
        asm volatile("cp.async.commit_group;" ::: "memory");                     \
    } while (0)

    LOAD_T(0, 0);
    LOAD_T(1, 1);
    const int NKT = 12;
    for (int kt = 0; kt < NKT; kt++) {
        int s = kt - (kt / 3) * 3;
        if (kt + 2 < NKT) asm volatile("cp.async.wait_group 1;" ::: "memory");
        else              asm volatile("cp.async.wait_group 0;" ::: "memory");
        __syncthreads();
        if (kt + 2 < NKT) {
            int s2 = (kt + 2) - ((kt + 2) / 3) * 3;
            LOAD_T(kt + 2, s2);
        }
        const char* sb = dsmT + (unsigned)s * T_STAGE;
        uint32_t ah[2][4];
#pragma unroll
        for (int mi = 0; mi < 2; mi++) {
            const char* pa = sb + (unsigned)((wm + mi * 16 + lrow8) * 48) + khalf;
            ldsm4(ah[mi][0], ah[mi][1], ah[mi][2], ah[mi][3], pa);
        }
        uint32_t bh[8][2];
#pragma unroll
        for (int p = 0; p < 4; p++) {
            const char* pb = sb + T_BOFF + (unsigned)((wn + p * 16 + lrow8) * 48) + khalf;
            ldsm4(bh[2 * p][0], bh[2 * p + 1][0], bh[2 * p][1], bh[2 * p + 1][1], pb);
        }
#pragma unroll
        for (int ni = 0; ni < 8; ni++)
#pragma unroll
            for (int mi = 0; mi < 2; mi++)
                mma_f16(acc[mi][ni], ah[mi], bh[ni][0], bh[ni][1]);
    }
#pragma unroll
    for (int mi = 0; mi < 2; mi++) {
        int r = mt * 128 + wm + mi * 16 + grp;
        int b0 = r >> 5, c0 = r & 31;
        int r1 = r + 8;
        int b1 = r1 >> 5, c1 = r1 & 31;
        __half* y0 = g_Yt16 + ((size_t)(b0 * H + h)) * LSEQ + c0 * CL;
        __half* y1 = g_Yt16 + ((size_t)(b1 * H + h)) * LSEQ + c1 * CL;
#pragma unroll
        for (int ni = 0; ni < 8; ni++) {
            int n = wn + ni * 8 + tq * 2;
            *(__half2*)(y0 + n) = __floats2half2_rn(gelu_f(acc[mi][ni][0]),
                                                    gelu_f(acc[mi][ni][1]));
            *(__half2*)(y1 + n) = __floats2half2_rn(gelu_f(acc[mi][ni][2]),
                                                    gelu_f(acc[mi][ni][3]));
        }
    }
}

// =====================================================================
// W prep: interleave rows, fp16.
// =====================================================================
__global__ __launch_bounds__(256) void w_prep(const float* __restrict__ W,
                                              const float* __restrict__ bp) {
    size_t i = (size_t)blockIdx.x * 256 + threadIdx.x;
    int col = (int)(i % H);
    int k   = (int)((i / H) % (2 * H));
    int l   = (int)(i / ((size_t)H * 2 * H));
    int orig = (k >> 1) + (k & 1) * H;
    float v = W[((size_t)l * 2 * H + orig) * H + col];
    g_Whi[i] = __float2half_rn(v);
    if (i < NLAY * 2 * H) {
        int kk = (int)(i % (2 * H));
        int ll = (int)(i / (2 * H));
        int og = (kk >> 1) + (kk & 1) * H;
        g_bint[i] = bp[ll * 2 * H + og];
    }
}

// =====================================================================
// conv GEMM + fused GLU: 1-term, A via ldmatrix.x4.trans from (B,H,L).
// =====================================================================
#define C_BOFF  4608u
#define C_STAGE 10752u
#define C_DSMEM (3 * C_STAGE)   /* 32256 */

__global__ __launch_bounds__(256, 2) void conv_gemm(int layer)
{
    extern __shared__ __align__(16) char dsm[];
    int tid = threadIdx.x;
    int warp = tid >> 5, lane = tid & 31;
    int grp = lane >> 2, tq = lane & 3;
    int n0 = blockIdx.x * 128, m0 = blockIdx.y * 128;
    int bB = m0 >> 12;
    int l0 = m0 & (LSEQ - 1);

    const __half* Wh = g_Whi + (size_t)layer * 2 * H * H;

    int wm = (warp >> 1) * 32, wn = (warp & 1) * 64;
    int lrow8 = (lane & 7) + (lane & 8);
    int khalf = (lane >> 4) * 16;
    int ktr = ((lane >> 4) & 1) * 8 + (lane & 7);
    int mby = ((lane >> 3) & 1) * 16;

    float acc[2][8][4];
#pragma unroll
    for (int mi = 0; mi < 2; mi++)
#pragma unroll
        for (int ni = 0; ni < 8; ni++)
#pragma unroll
            for (int r = 0; r < 4; r++) acc[mi][ni][r] = 0.0f;

    int fa_r = tid >> 4, fa_c = tid & 15;
    int fb_r = tid >> 1, fb_c = tid & 1;

#define LOAD_C(KT, S)                                                            \
    do {                                                                         \
        char* sb = dsm + (unsigned)(S) * C_STAGE;                                \
        cpa16(sb + (unsigned)(fa_r * 272 + fa_c * 16),                           \
              g_Yt16 + ((size_t)(bB * H + (KT) * 16 + fa_r)) * LSEQ + l0 + fa_c * 8); \
        cpa16(sb + C_BOFF + (unsigned)(fb_r * 48 + fb_c * 16),                   \
              Wh + (size_t)(n0 + fb_r) * H + (KT) * 16 + fb_c * 8);              \
        asm volatile("cp.async.commit_group;" ::: "memory");                     \
    } while (0)

    LOAD_C(0, 0);
    LOAD_C(1, 1);

    const int NKT = H / 16;   // 32
    for (int kt = 0; kt < NKT; kt++) {
        int s = kt - (kt / 3) * 3;
        if (kt + 2 < NKT) asm volatile("cp.async.wait_group 1;" ::: "memory");
        else              asm volatile("cp.async.wait_group 0;" ::: "memory");
        __syncthreads();
        if (kt + 2 < NKT) {
            int s2 = (kt + 2) - ((kt + 2) / 3) * 3;
            LOAD_C(kt + 2, s2);
        }
        const char* sb = dsm + (unsigned)s * C_STAGE;
        uint32_t ah[2][4];
#pragma unroll
        for (int mi = 0; mi < 2; mi++) {
            const char* pa = sb + (unsigned)(ktr * 272 + (wm + mi * 16) * 2 + mby);
            ldsm4t(ah[mi][0], ah[mi][1], ah[mi][2], ah[mi][3], pa);
        }
        uint32_t bh[8][2];
#pragma unroll
        for (int p = 0; p < 4; p++) {
            const char* pb = sb + C_BOFF + (unsigned)((wn + p * 16 + lrow8) * 48) + khalf;
            ldsm4(bh[2 * p][0], bh[2 * p + 1][0], bh[2 * p][1], bh[2 * p + 1][1], pb);
        }
#pragma unroll
        for (int ni = 0; ni < 8; ni++)
#pragma unroll
            for (int mi = 0; mi < 2; mi++)
                mma_f16(acc[mi][ni], ah[mi], bh[ni][0], bh[ni][1]);
    }
#pragma unroll
    for (int mi = 0; mi < 2; mi++)
#pragma unroll
        for (int ni = 0; ni < 8; ni++) {
            int r  = m0 + wm + mi * 16 + grp;
            int cb = wn + ni * 8 + tq * 2;
            float ba = g_bint[layer * 2 * H + n0 + cb];
            float bg = g_bint[layer * 2 * H + n0 + cb + 1];
            float a0 = acc[mi][ni][0] + ba, gg0 = acc[mi][ni][1] + bg;
            float a1 = acc[mi][ni][2] + ba, gg1 = acc[mi][ni][3] + bg;
            int hidx = (n0 + cb) >> 1;
            g_Zh[(size_t)r * H + hidx]       = __float2half_rn(a0 / (1.0f + expf(-gg0)));
            g_Zh[(size_t)(r + 8) * H + hidx] = __float2half_rn(a1 / (1.0f + expf(-gg1)));
        }
}

// =====================================================================
// res_ln_final: residual (fp16 xin) + LN -> fp32 out. warp per row.
// =====================================================================
__global__ __launch_bounds__(128) void res_ln_final(
    const __half* __restrict__ xin, float* __restrict__ xout,
    const float* __restrict__ gamma, const float* __restrict__ beta, int layer)
{
    int row  = blockIdx.x * 4 + (threadIdx.x >> 5);
    int lane = threadIdx.x & 31;
    const __half2* zh = (const __half2*)(g_Zh + (size_t)row * H);
    const __half2* xh = (const __half2*)(xin + (size_t)row * H);
    float4* o4       = (float4*)(xout + (size_t)row * H);
    const float4* g4 = (const float4*)(gamma + layer * H);
    const float4* e4 = (const float4*)(beta + layer * H);

    float4 v[4];
    float s = 0.0f, s2 = 0.0f;
#pragma unroll
    for (int j = 0; j < 4; j++) {
        __half2 p0 = zh[(j * 32 + lane) * 2];
        __half2 p1 = zh[(j * 32 + lane) * 2 + 1];
        __half2 x0 = xh[(j * 32 + lane) * 2];
        __half2 x1 = xh[(j * 32 + lane) * 2 + 1];
        float4 vv;
        vv.x = __low2float(p0) + __low2float(x0);
        vv.y = __high2float(p0) + __high2float(x0);
        vv.z = __low2float(p1) + __low2float(x1);
        vv.w = __high2float(p1) + __high2float(x1);
        v[j] = vv;
        s += vv.x + vv.y + vv.z + vv.w;
        s2 = fmaf(vv.x, vv.x, s2); s2 = fmaf(vv.y, vv.y, s2);
        s2 = fmaf(vv.z, vv.z, s2); s2 = fmaf(vv.w, vv.w, s2);
    }
#pragma unroll
    for (int o = 16; o; o >>= 1) {
        s  += __shfl_xor_sync(0xffffffffu, s, o);
        s2 += __shfl_xor_sync(0xffffffffu, s2, o);
    }
    float mu = s * (1.0f / H);
    float rs = rsqrtf(s2 * (1.0f / H) - mu * mu + LN_EPS);
#pragma unroll
    for (int j = 0; j < 4; j++) {
        float4 ga = g4[j * 32 + lane];
        float4 be = e4[j * 32 + lane];
        float4 vv = v[j], o;
        o.x = (vv.x - mu) * rs * ga.x + be.x;
        o.y = (vv.y - mu) * rs * ga.y + be.y;
        o.z = (vv.z - mu) * rs * ga.z + be.z;
        o.w = (vv.w - mu) * rs * ga.w + be.w;
        o4[j * 32 + lane] = o;
    }
}

// =====================================================================
// res_lnT (layers 0..2): residual + LN; fp16 xout (B,L,H) and
// transposed fp16 U plane (B,H,L). IN32: layer 0 reads fp32 x.
// =====================================================================
#define RL_SMEM (32 * 513 * 4)   /* 65664 */
template <int IN32>
__global__ __launch_bounds__(256) void res_lnT(
    const float* __restrict__ xin32, const __half* __restrict__ xin16,
    __half* __restrict__ xout16,
    const float* __restrict__ gamma, const float* __restrict__ beta, int layer)
{
    extern __shared__ float sv[];    // [32][513]
    int warp = threadIdx.x >> 5, lane = threadIdx.x & 31;
    int row0 = blockIdx.x * 32;
    int b = row0 >> 12;
    int l0 = row0 & (LSEQ - 1);
    const float4* g4 = (const float4*)(gamma + layer * H);
    const float4* e4 = (const float4*)(beta + layer * H);

#pragma unroll
    for (int i = 0; i < 4; i++) {
        int lr = warp * 4 + i;
        int row = row0 + lr;
        const __half2* zh = (const __half2*)(g_Zh + (size_t)row * H);
        __half2* oh = (__half2*)(xout16 + (size_t)row * H);
        float4 v[4];
        float s = 0.0f, s2 = 0.0f;
#pragma unroll
        for (int j = 0; j < 4; j++) {
            __half2 p0 = zh[(j * 32 + lane) * 2];
            __half2 p1 = zh[(j * 32 + lane) * 2 + 1];
            float4 xv;
            if (IN32) {
                xv = ((const float4*)(xin32 + (size_t)row * H))[j * 32 + lane];
            } else {
                const __half2* xh = (const __half2*)(xin16 + (size_t)row * H);
                __half2 x0 = xh[(j * 32 + lane) * 2];
                __half2 x1 = xh[(j * 32 + lane) * 2 + 1];
                xv.x = __low2float(x0); xv.y = __high2float(x0);
                xv.z = __low2float(x1); xv.w = __high2float(x1);
            }
            float4 vv;
            vv.x = __low2float(p0)  + xv.x; vv.y = __high2float(p0) + xv.y;
            vv.z = __low2float(p1)  + xv.z; vv.w = __high2float(p1) + xv.w;
            v[j] = vv;
            s += vv.x + vv.y + vv.z + vv.w;
            s2 = fmaf(vv.x, vv.x, s2); s2 = fmaf(vv.y, vv.y, s2);
            s2 = fmaf(vv.z, vv.z, s2); s2 = fmaf(vv.w, vv.w, s2);
        }
#pragma unroll
        for (int o = 16; o; o >>= 1) {
            s  += __shfl_xor_sync(0xffffffffu, s, o);
            s2 += __shfl_xor_sync(0xffffffffu, s2, o);
        }
        float mu = s * (1.0f / H);
        float rs = rsqrtf(s2 * (1.0f / H) - mu * mu + LN_EPS);
#pragma unroll
        for (int j = 0; j < 4; j++) {
            float4 ga = g4[j * 32 + lane];
            float4 be = e4[j * 32 + lane];
            float4 vv = v[j], o;
            o.x = (vv.x - mu) * rs * ga.x + be.x;
            o.y = (vv.y - mu) * rs * ga.y + be.y;
            o.z = (vv.z - mu) * rs * ga.z + be.z;
            o.w = (vv.w - mu) * rs * ga.w + be.w;
            oh[(j * 32 + lane) * 2]     = __floats2half2_rn(o.x, o.y);
            oh[(j * 32 + lane) * 2 + 1] = __floats2half2_rn(o.z, o.w);
            int hh = (j * 32 + lane) * 4;
            sv[lr * 513 + hh + 0] = o.x;
            sv[lr * 513 + hh + 1] = o.y;
            sv[lr * 513 + hh + 2] = o.z;
            sv[lr * 513 + hh + 3] = o.w;
        }
    }
    __syncthreads();
#pragma unroll 4
    for (int it = 0; it < 64; it++) {
        int h = it * 8 + warp;
        float v = sv[lane * 513 + h];
        g_Uhi[((size_t)(b * H + h)) * LSEQ + l0 + lane] = __float2half_rn(v);
    }
}

// ================= launcher =================
extern "C" void kernel_launch(void* const* d_in, const int* in_sizes, int n_in,
                              void* d_out, int out_size)
{
    const float* x          = (const float*)d_in[0];
    const float* log_dt     = (const float*)d_in[1];
    const float* A_imag     = (const float*)d_in[2];
    const float* log_A_real = (const float*)d_in[3];
    const float* C          = (const float*)d_in[4];
    const float* D          = (const float*)d_in[5];
    const float* W          = (const float*)d_in[6];
    const float* bconv      = (const float*)d_in[7];
    const float* gamma      = (const float*)d_in[8];
    const float* beta       = (const float*)d_in[9];
    float* out = (float*)d_out;

    cudaFuncSetAttribute(conv_gemm, cudaFuncAttributeMaxDynamicSharedMemorySize,
                         C_DSMEM);
    cudaFuncSetAttribute(gemm_toep, cudaFuncAttributeMaxDynamicSharedMemorySize,
                         T_DSMEM);
    cudaFuncSetAttribute(gemm_endpre, cudaFuncAttributeMaxDynamicSharedMemorySize,
                         EP_DSMEM);
    cudaFuncSetAttribute(res_lnT<0>, cudaFuncAttributeMaxDynamicSharedMemorySize,
                         RL_SMEM);
    cudaFuncSetAttribute(res_lnT<1>, cudaFuncAttributeMaxDynamicSharedMemorySize,
                         RL_SMEM);

    __half* pA; cudaGetSymbolAddress((void**)&pA, g_x16A);
    __half* pB; cudaGetSymbolAddress((void**)&pB, g_x16B);

    w_prep<<<(NLAY * 2 * H * H) / 256, 256>>>(W, bconv);
    tbuild<<<dim3(H, NLAY), 256>>>(log_dt, A_imag, log_A_real, C, D);

    dim3 tb(32, 8);
    xsplit<<<dim3(H / 32, LSEQ / 32, BSZ), tb>>>(x);   // layer-0 U plane

    for (int i = 0; i < NLAY; i++) {
        gemm_endpre<<<H, 256, EP_DSMEM>>>(log_dt, A_imag, log_A_real, i);
        gemm_toep<<<dim3(2, H), 256, T_DSMEM>>>(i);
        conv_gemm<<<dim3(2 * H / 128, MROWS / 128), 256, C_DSMEM>>>(i);
        if (i == 0)
            res_lnT<1><<<MROWS / 32, 256, RL_SMEM>>>(x, nullptr, pA,
                                                     gamma, beta, 0);
        else if (i == 1)
            res_lnT<0><<<MROWS / 32, 256, RL_SMEM>>>(nullptr, pA, pB,
                                                     gamma, beta, 1);
        else if (i == 2)
            res_lnT<0><<<MROWS / 32, 256, RL_SMEM>>>(nullptr, pB, pA,
                                                     gamma, beta, 2);
        else
            res_ln_final<<<MROWS / 4, 128>>>(pA, out, gamma, beta, 3);
    }
}